// round 1
// baseline (speedup 1.0000x reference)
#include <cuda_runtime.h>
#include <cuda_bf16.h>
#include <math.h>

// Problem constants
#define LT   110592   // total tokens = 48*48*48
#define CD   96       // channels
#define NS   2304     // attention sequence length (H*W)
#define DA   1536     // attention feature dim (B_*hd)
#define NHD  3        // heads
#define HIDD 384      // mlp hidden
#define QK_SCALE 0.17677669529663687f  // 32^-0.5

// Scratch buffers (device globals: allocation APIs are banned)
__device__ float g_ln1[(size_t)LT * CD];
__device__ float g_qkv[(size_t)LT * 3 * CD];      // [110592, 288] == [N, B_, 3C] flat
__device__ float g_S  [(size_t)NHD * NS * NS];    // attention logits/probs
__device__ float g_O  [(size_t)NS * NHD * DA];    // [n, head*1536+j] == flat [110592, 96]
__device__ float g_x2 [(size_t)LT * CD];          // x + attn out
__device__ float g_ln2[(size_t)LT * CD];
__device__ float g_hid[(size_t)LT * HIDD];

// ---------------------------------------------------------------------------
// LayerNorm: one warp per row of 96
// ---------------------------------------------------------------------------
__global__ void ln_kernel(const float* __restrict__ x, const float* __restrict__ g,
                          const float* __restrict__ b, float* __restrict__ out) {
    int wid  = (blockIdx.x * blockDim.x + threadIdx.x) >> 5;
    int lane = threadIdx.x & 31;
    if (wid >= LT) return;
    const float* row = x + (size_t)wid * CD;
    float v0 = row[lane], v1 = row[lane + 32], v2 = row[lane + 64];
    float s = v0 + v1 + v2;
    #pragma unroll
    for (int o = 16; o > 0; o >>= 1) s += __shfl_xor_sync(0xffffffffu, s, o);
    float mean = s * (1.0f / 96.0f);
    float d0 = v0 - mean, d1 = v1 - mean, d2 = v2 - mean;
    float vs = d0 * d0 + d1 * d1 + d2 * d2;
    #pragma unroll
    for (int o = 16; o > 0; o >>= 1) vs += __shfl_xor_sync(0xffffffffu, vs, o);
    float rstd = rsqrtf(vs * (1.0f / 96.0f) + 1e-5f);
    float* orow = out + (size_t)wid * CD;
    orow[lane]      = d0 * rstd * g[lane]      + b[lane];
    orow[lane + 32] = d1 * rstd * g[lane + 32] + b[lane + 32];
    orow[lane + 64] = d2 * rstd * g[lane + 64] + b[lane + 64];
}

// ---------------------------------------------------------------------------
// SGEMM  C = alpha * A @ B^T (+ epilogue). A:[M,K] lda, B:[N,K] ldb.
// EPI: 0 none, 1 +bias, 2 +bias+gelu, 3 +bias+residual
// ---------------------------------------------------------------------------
template<int BM, int BN, int BK, int TM, int TN, int EPI>
__global__ void __launch_bounds__(256) sgemm_nt(
    const float* __restrict__ A, int lda, long aZ,
    const float* __restrict__ B, int ldb, long bZ,
    const float* __restrict__ bias, const float* __restrict__ res,
    float* __restrict__ Cp, int ldc, long cZ,
    int K, float alpha)
{
    __shared__ float As[BK][BM];
    __shared__ float Bs[BK][BN];
    const int tid = threadIdx.x;
    const int i0 = blockIdx.y * BM;
    const int n0 = blockIdx.x * BN;
    A  += (size_t)blockIdx.z * aZ;
    B  += (size_t)blockIdx.z * bZ;
    Cp += (size_t)blockIdx.z * cZ;

    const int tx = tid & 15;
    const int ty = tid >> 4;

    float acc[TM][TN];
    #pragma unroll
    for (int i = 0; i < TM; i++)
        #pragma unroll
        for (int j = 0; j < TN; j++) acc[i][j] = 0.0f;

    const int nK = K / BK;
    for (int kt = 0; kt < nK; kt++) {
        #pragma unroll
        for (int e = tid; e < (BM * BK) / 4; e += 256) {
            int m = e >> 1;            // BK=8 -> 2 float4 per row
            int kq = (e & 1) * 4;
            float4 v = *reinterpret_cast<const float4*>(
                A + (size_t)(i0 + m) * lda + kt * BK + kq);
            As[kq + 0][m] = v.x; As[kq + 1][m] = v.y;
            As[kq + 2][m] = v.z; As[kq + 3][m] = v.w;
        }
        #pragma unroll
        for (int e = tid; e < (BN * BK) / 4; e += 256) {
            int n = e >> 1;
            int kq = (e & 1) * 4;
            float4 v = *reinterpret_cast<const float4*>(
                B + (size_t)(n0 + n) * ldb + kt * BK + kq);
            Bs[kq + 0][n] = v.x; Bs[kq + 1][n] = v.y;
            Bs[kq + 2][n] = v.z; Bs[kq + 3][n] = v.w;
        }
        __syncthreads();
        #pragma unroll
        for (int k = 0; k < BK; k++) {
            float ar[TM], br[TN];
            #pragma unroll
            for (int i = 0; i < TM; i++) ar[i] = As[k][ty * TM + i];
            #pragma unroll
            for (int j = 0; j < TN; j++) br[j] = Bs[k][tx * TN + j];
            #pragma unroll
            for (int i = 0; i < TM; i++)
                #pragma unroll
                for (int j = 0; j < TN; j++)
                    acc[i][j] = fmaf(ar[i], br[j], acc[i][j]);
        }
        __syncthreads();
    }

    #pragma unroll
    for (int i = 0; i < TM; i++) {
        int row = i0 + ty * TM + i;
        #pragma unroll
        for (int j = 0; j < TN; j++) {
            int col = n0 + tx * TN + j;
            float v = acc[i][j] * alpha;
            if (EPI >= 1) v += bias[col];
            if (EPI == 2) v = 0.5f * v * (1.0f + erff(v * 0.70710678118654752f));
            if (EPI == 3) v += res[(size_t)row * ldc + col];
            Cp[(size_t)row * ldc + col] = v;
        }
    }
}

// ---------------------------------------------------------------------------
// SGEMM  C = A @ B (NN). A:[M,K] lda, B:[K,N] ldb. 128x128x8 tiles.
// ---------------------------------------------------------------------------
__global__ void __launch_bounds__(256) sgemm_nn128(
    const float* __restrict__ A, int lda, long aZ,
    const float* __restrict__ B, int ldb, long bZ,
    float* __restrict__ Cp, int ldc, long cZ, int K)
{
    constexpr int BM = 128, BN = 128, BK = 8, TM = 8, TN = 8;
    __shared__ float As[BK][BM];
    __shared__ float Bs[BK][BN];
    const int tid = threadIdx.x;
    const int i0 = blockIdx.y * BM;
    const int n0 = blockIdx.x * BN;
    A  += (size_t)blockIdx.z * aZ;
    B  += (size_t)blockIdx.z * bZ;
    Cp += (size_t)blockIdx.z * cZ;

    const int tx = tid & 15;
    const int ty = tid >> 4;

    float acc[TM][TN];
    #pragma unroll
    for (int i = 0; i < TM; i++)
        #pragma unroll
        for (int j = 0; j < TN; j++) acc[i][j] = 0.0f;

    const int nK = K / BK;
    for (int kt = 0; kt < nK; kt++) {
        {
            int m = tid >> 1;
            int kq = (tid & 1) * 4;
            float4 v = *reinterpret_cast<const float4*>(
                A + (size_t)(i0 + m) * lda + kt * BK + kq);
            As[kq + 0][m] = v.x; As[kq + 1][m] = v.y;
            As[kq + 2][m] = v.z; As[kq + 3][m] = v.w;
        }
        {
            int k = tid >> 5;
            int n4 = (tid & 31) * 4;
            float4 v = *reinterpret_cast<const float4*>(
                B + (size_t)(kt * BK + k) * ldb + n0 + n4);
            *reinterpret_cast<float4*>(&Bs[k][n4]) = v;
        }
        __syncthreads();
        #pragma unroll
        for (int k = 0; k < BK; k++) {
            float ar[TM], br[TN];
            #pragma unroll
            for (int i = 0; i < TM; i++) ar[i] = As[k][ty * TM + i];
            #pragma unroll
            for (int j = 0; j < TN; j++) br[j] = Bs[k][tx * TN + j];
            #pragma unroll
            for (int i = 0; i < TM; i++)
                #pragma unroll
                for (int j = 0; j < TN; j++)
                    acc[i][j] = fmaf(ar[i], br[j], acc[i][j]);
        }
        __syncthreads();
    }

    #pragma unroll
    for (int i = 0; i < TM; i++) {
        int row = i0 + ty * TM + i;
        #pragma unroll
        for (int j = 0; j < TN; j++) {
            int col = n0 + tx * TN + j;
            Cp[(size_t)row * ldc + col] = acc[i][j];
        }
    }
}

// ---------------------------------------------------------------------------
// Row softmax over 2304 cols. One block (256 threads, 9 elems/thread) per row.
// ---------------------------------------------------------------------------
__global__ void softmax_kernel(float* __restrict__ S) {
    const int row = blockIdx.x;
    float* p = S + (size_t)row * NS;
    const int tid = threadIdx.x;
    __shared__ float sm[8], ss[8];

    float v[9];
    float mx = -3.4e38f;
    #pragma unroll
    for (int i = 0; i < 9; i++) { v[i] = p[tid + 256 * i]; mx = fmaxf(mx, v[i]); }
    #pragma unroll
    for (int o = 16; o > 0; o >>= 1) mx = fmaxf(mx, __shfl_xor_sync(0xffffffffu, mx, o));
    if ((tid & 31) == 0) sm[tid >> 5] = mx;
    __syncthreads();
    mx = sm[0];
    #pragma unroll
    for (int i = 1; i < 8; i++) mx = fmaxf(mx, sm[i]);

    float sum = 0.0f;
    #pragma unroll
    for (int i = 0; i < 9; i++) { v[i] = __expf(v[i] - mx); sum += v[i]; }
    #pragma unroll
    for (int o = 16; o > 0; o >>= 1) sum += __shfl_xor_sync(0xffffffffu, sum, o);
    if ((tid & 31) == 0) ss[tid >> 5] = sum;
    __syncthreads();
    sum = 0.0f;
    #pragma unroll
    for (int i = 0; i < 8; i++) sum += ss[i];
    float inv = 1.0f / sum;
    #pragma unroll
    for (int i = 0; i < 9; i++) p[tid + 256 * i] = v[i] * inv;
}

// ---------------------------------------------------------------------------
extern "C" void kernel_launch(void* const* d_in, const int* in_sizes, int n_in,
                              void* d_out, int out_size) {
    const float* x      = (const float*)d_in[0];
    // d_in[1] = mask_matrix (unused, zeros)
    const float* ln1_g  = (const float*)d_in[2];
    const float* ln1_b  = (const float*)d_in[3];
    const float* qkv_w  = (const float*)d_in[4];
    const float* qkv_b  = (const float*)d_in[5];
    const float* proj_w = (const float*)d_in[6];
    const float* proj_b = (const float*)d_in[7];
    const float* ln2_g  = (const float*)d_in[8];
    const float* ln2_b  = (const float*)d_in[9];
    const float* fc1_w  = (const float*)d_in[10];
    const float* fc1_b  = (const float*)d_in[11];
    const float* fc2_w  = (const float*)d_in[12];
    const float* fc2_b  = (const float*)d_in[13];
    float* out = (float*)d_out;

    float *p_ln1, *p_qkv, *p_S, *p_O, *p_x2, *p_ln2, *p_hid;
    cudaGetSymbolAddress((void**)&p_ln1, g_ln1);
    cudaGetSymbolAddress((void**)&p_qkv, g_qkv);
    cudaGetSymbolAddress((void**)&p_S,   g_S);
    cudaGetSymbolAddress((void**)&p_O,   g_O);
    cudaGetSymbolAddress((void**)&p_x2,  g_x2);
    cudaGetSymbolAddress((void**)&p_ln2, g_ln2);
    cudaGetSymbolAddress((void**)&p_hid, g_hid);

    // 1. LN1: x -> g_ln1   (attention row r = n*48+t maps to x row l = r: identity)
    ln_kernel<<<LT / 8, 256>>>(x, ln1_g, ln1_b, p_ln1);

    // 2. QKV GEMM: [110592,96]@[96,288]^T + bias -> g_qkv (== [N, B_, 3C] flat)
    sgemm_nt<128, 96, 8, 8, 6, 1><<<dim3(3, LT / 128, 1), 256>>>(
        p_ln1, CD, 0, qkv_w, CD, 0, qkv_b, nullptr, p_qkv, 3 * CD, 0, CD, 1.0f);

    // 3. Logits: S[h] = scale * Q[h] @ K[h]^T; Q row n = g_qkv[n*13824 + h*1536]
    sgemm_nt<128, 128, 8, 8, 8, 0><<<dim3(NS / 128, NS / 128, NHD), 256>>>(
        p_qkv, 3 * CD * 48, DA, p_qkv + 3 * DA, 3 * CD * 48, DA,
        nullptr, nullptr, p_S, NS, (long)NS * NS, DA, QK_SCALE);

    // 4. Row softmax over all 3*2304 rows
    softmax_kernel<<<NHD * NS, 256>>>(p_S);

    // 5. O[h] = P[h] @ V[h];  V row j = g_qkv[j*13824 + 9216 + h*1536]
    //    stored as g_O[n*4608 + h*1536 + d]  (flat == proj input [110592, 96])
    sgemm_nn128<<<dim3(DA / 128, NS / 128, NHD), 256>>>(
        p_S, NS, (long)NS * NS, p_qkv + 6 * DA, 3 * CD * 48, DA,
        p_O, NHD * DA, DA, NS);

    // 6. proj + bias + residual(x) -> g_x2   (pure flat view, no gather)
    sgemm_nt<128, 96, 8, 8, 6, 3><<<dim3(1, LT / 128, 1), 256>>>(
        p_O, CD, 0, proj_w, CD, 0, proj_b, x, p_x2, CD, 0, CD, 1.0f);

    // 7. LN2
    ln_kernel<<<LT / 8, 256>>>(p_x2, ln2_g, ln2_b, p_ln2);

    // 8. fc1 + bias + exact GELU -> g_hid
    sgemm_nt<128, 96, 8, 8, 6, 2><<<dim3(HIDD / 96, LT / 128, 1), 256>>>(
        p_ln2, CD, 0, fc1_w, CD, 0, fc1_b, nullptr, p_hid, HIDD, 0, CD, 1.0f);

    // 9. fc2 + bias + residual(g_x2) -> out
    sgemm_nt<128, 96, 8, 8, 6, 3><<<dim3(1, LT / 128, 1), 256>>>(
        p_hid, HIDD, 0, fc2_w, HIDD, 0, fc2_b, p_x2, out, CD, 0, HIDD, 1.0f);
}

// round 2
// speedup vs baseline: 4.9859x; 4.9859x over previous
#include <cuda_runtime.h>
#include <cuda_bf16.h>
#include <math.h>
#include <stdint.h>

// Problem constants
#define LT   110592   // tokens = 48*48*48
#define CD   96       // channels
#define NS   2304     // attention sequence length (H*W)
#define DA   1536     // attention feature dim (B_*hd)
#define NHD  3        // heads
#define HIDD 384      // mlp hidden
#define QK_SCALE 0.17677669529663687f

// Scratch (device globals; alloc APIs banned)
__device__ __nv_bfloat16 g_ln1b[(size_t)LT * CD];
__device__ __nv_bfloat16 g_qkvb[(size_t)LT * 3 * CD];   // [N, B_, 3C] flat, bf16
__device__ float         g_S   [(size_t)NHD * NS * NS]; // logits fp32
__device__ __nv_bfloat16 g_Pb  [(size_t)NHD * NS * NS]; // probs bf16
__device__ __nv_bfloat16 g_Ob  [(size_t)NS * NHD * DA]; // attn out == flat [110592,96]
__device__ float         g_x2  [(size_t)LT * CD];
__device__ __nv_bfloat16 g_ln2b[(size_t)LT * CD];
__device__ __nv_bfloat16 g_hidb[(size_t)LT * HIDD];
__device__ __nv_bfloat16 g_wqkv[3 * CD * CD];
__device__ __nv_bfloat16 g_wproj[CD * CD];
__device__ __nv_bfloat16 g_wfc1[HIDD * CD];
__device__ __nv_bfloat16 g_wfc2[CD * HIDD];

// ---------------------------------------------------------------------------
__device__ __forceinline__ uint32_t s2u(const void* p) {
    return (uint32_t)__cvta_generic_to_shared(p);
}
__device__ __forceinline__ void ldsm4(uint32_t& r0, uint32_t& r1, uint32_t& r2, uint32_t& r3, uint32_t a) {
    asm volatile("ldmatrix.sync.aligned.m8n8.x4.shared.b16 {%0,%1,%2,%3}, [%4];\n"
                 : "=r"(r0), "=r"(r1), "=r"(r2), "=r"(r3) : "r"(a));
}
__device__ __forceinline__ void ldsm4t(uint32_t& r0, uint32_t& r1, uint32_t& r2, uint32_t& r3, uint32_t a) {
    asm volatile("ldmatrix.sync.aligned.m8n8.x4.trans.shared.b16 {%0,%1,%2,%3}, [%4];\n"
                 : "=r"(r0), "=r"(r1), "=r"(r2), "=r"(r3) : "r"(a));
}
__device__ __forceinline__ void mma16816(float* c, const uint32_t* a, const uint32_t* b) {
    asm volatile("mma.sync.aligned.m16n8k16.row.col.f32.bf16.bf16.f32 "
                 "{%0,%1,%2,%3}, {%4,%5,%6,%7}, {%8,%9}, {%0,%1,%2,%3};\n"
                 : "+f"(c[0]), "+f"(c[1]), "+f"(c[2]), "+f"(c[3])
                 : "r"(a[0]), "r"(a[1]), "r"(a[2]), "r"(a[3]), "r"(b[0]), "r"(b[1]));
}

// ---------------------------------------------------------------------------
// LayerNorm: one warp per row of 96, bf16 out
// ---------------------------------------------------------------------------
__global__ void ln_kernel(const float* __restrict__ x, const float* __restrict__ g,
                          const float* __restrict__ b, __nv_bfloat16* __restrict__ out) {
    int wid  = (blockIdx.x * blockDim.x + threadIdx.x) >> 5;
    int lane = threadIdx.x & 31;
    if (wid >= LT) return;
    const float* row = x + (size_t)wid * CD;
    float v0 = row[lane], v1 = row[lane + 32], v2 = row[lane + 64];
    float s = v0 + v1 + v2;
    #pragma unroll
    for (int o = 16; o > 0; o >>= 1) s += __shfl_xor_sync(0xffffffffu, s, o);
    float mean = s * (1.0f / 96.0f);
    float d0 = v0 - mean, d1 = v1 - mean, d2 = v2 - mean;
    float vs = d0 * d0 + d1 * d1 + d2 * d2;
    #pragma unroll
    for (int o = 16; o > 0; o >>= 1) vs += __shfl_xor_sync(0xffffffffu, vs, o);
    float rstd = rsqrtf(vs * (1.0f / 96.0f) + 1e-5f);
    __nv_bfloat16* orow = out + (size_t)wid * CD;
    orow[lane]      = __float2bfloat16(d0 * rstd * g[lane]      + b[lane]);
    orow[lane + 32] = __float2bfloat16(d1 * rstd * g[lane + 32] + b[lane + 32]);
    orow[lane + 64] = __float2bfloat16(d2 * rstd * g[lane + 64] + b[lane + 64]);
}

// fp32 -> bf16 conversion (weights)
__global__ void f2bf(const float* __restrict__ s, __nv_bfloat16* __restrict__ d, int n) {
    int i = blockIdx.x * blockDim.x + threadIdx.x;
    if (i < n) d[i] = __float2bfloat16(s[i]);
}

// ---------------------------------------------------------------------------
// Row softmax over 2304 cols (fp32 in, bf16 out). One block per row.
// ---------------------------------------------------------------------------
__global__ void softmax_kernel(const float* __restrict__ S, __nv_bfloat16* __restrict__ P) {
    const int row = blockIdx.x;
    const float* p = S + (size_t)row * NS;
    __nv_bfloat16* q = P + (size_t)row * NS;
    const int tid = threadIdx.x;
    __shared__ float sm[8], ss[8];

    float v[9];
    float mx = -3.4e38f;
    #pragma unroll
    for (int i = 0; i < 9; i++) { v[i] = p[tid + 256 * i]; mx = fmaxf(mx, v[i]); }
    #pragma unroll
    for (int o = 16; o > 0; o >>= 1) mx = fmaxf(mx, __shfl_xor_sync(0xffffffffu, mx, o));
    if ((tid & 31) == 0) sm[tid >> 5] = mx;
    __syncthreads();
    mx = sm[0];
    #pragma unroll
    for (int i = 1; i < 8; i++) mx = fmaxf(mx, sm[i]);

    float sum = 0.0f;
    #pragma unroll
    for (int i = 0; i < 9; i++) { v[i] = __expf(v[i] - mx); sum += v[i]; }
    #pragma unroll
    for (int o = 16; o > 0; o >>= 1) sum += __shfl_xor_sync(0xffffffffu, sum, o);
    if ((tid & 31) == 0) ss[tid >> 5] = sum;
    __syncthreads();
    sum = 0.0f;
    #pragma unroll
    for (int i = 0; i < 8; i++) sum += ss[i];
    float inv = 1.0f / sum;
    #pragma unroll
    for (int i = 0; i < 9; i++) q[tid + 256 * i] = __float2bfloat16(v[i] * inv);
}

// ---------------------------------------------------------------------------
// bf16 MMA GEMM.  C = alpha * A @ op(B)  (+ epilogue)
//   A: row-major [M,K] bf16
//   BNN=false: B is [N,K] bf16 (NT, C = A@B^T)
//   BNN=true : B is [K,N] bf16 (NN)
// EPI: 0 none, 1 +bias, 2 +bias+gelu, 3 +bias+residual
// OBF: true -> bf16 out, false -> fp32 out
// ---------------------------------------------------------------------------
template<int BM, int BN, bool BNN, int EPI, bool OBF>
__global__ void __launch_bounds__(256) mma_gemm(
    const __nv_bfloat16* __restrict__ A, int lda, long aZ,
    const __nv_bfloat16* __restrict__ B, int ldb, long bZ,
    const float* __restrict__ bias, const float* __restrict__ res,
    void* __restrict__ Cout, int ldc, long cZ, int K, float alpha)
{
    constexpr int BK = 32;
    constexpr int WM = 4, WN = 2;
    constexpr int WMT = BM / WM;     // 32
    constexpr int WNT = BN / WN;     // 64 or 48
    constexpr int MI = WMT / 16;     // 2
    constexpr int NI = WNT / 8;      // 8 or 6
    constexpr int THREADS = 256;
    constexpr int BSR = BNN ? BK : BN;
    constexpr int BSC = BNN ? BN + 8 : BK + 8;

    __shared__ __nv_bfloat16 As[BM][BK + 8];
    __shared__ __nv_bfloat16 Bs[BSR][BSC];

    const int tid  = threadIdx.x;
    const int wid  = tid >> 5;
    const int lane = tid & 31;
    const int wm = wid / WN, wn = wid % WN;
    const int i0 = blockIdx.y * BM;
    const int n0 = blockIdx.x * BN;
    A += (size_t)blockIdx.z * aZ;
    B += (size_t)blockIdx.z * bZ;

    float c[MI][NI][4];
    #pragma unroll
    for (int mi = 0; mi < MI; mi++)
        #pragma unroll
        for (int ni = 0; ni < NI; ni++)
            #pragma unroll
            for (int e = 0; e < 4; e++) c[mi][ni][e] = 0.0f;

    const int nKT = K / BK;
    for (int kt = 0; kt < nKT; kt++) {
        // A tile: BM x 32, uint4 = 8 bf16
        #pragma unroll
        for (int e = tid; e < BM * 4; e += THREADS) {
            int m = e >> 2, kv = e & 3;
            *(uint4*)&As[m][kv * 8] =
                *(const uint4*)(A + (size_t)(i0 + m) * lda + kt * BK + kv * 8);
        }
        if (!BNN) {
            #pragma unroll
            for (int e = tid; e < BN * 4; e += THREADS) {
                int n = e >> 2, kv = e & 3;
                *(uint4*)&Bs[n][kv * 8] =
                    *(const uint4*)(B + (size_t)(n0 + n) * ldb + kt * BK + kv * 8);
            }
        } else {
            #pragma unroll
            for (int e = tid; e < BK * (BN / 8); e += THREADS) {
                int k = e / (BN / 8), nv = e % (BN / 8);
                *(uint4*)&Bs[k][nv * 8] =
                    *(const uint4*)(B + (size_t)(kt * BK + k) * ldb + n0 + nv * 8);
            }
        }
        __syncthreads();

        #pragma unroll
        for (int kk = 0; kk < 2; kk++) {           // two k16 steps per BK=32
            uint32_t a[MI][4];
            #pragma unroll
            for (int mi = 0; mi < MI; mi++) {
                int m  = wm * WMT + mi * 16 + (lane & 15);
                int kc = kk * 16 + (lane >> 4) * 8;
                ldsm4(a[mi][0], a[mi][1], a[mi][2], a[mi][3], s2u(&As[m][kc]));
            }
            uint32_t b[NI][2];
            #pragma unroll
            for (int np = 0; np < NI / 2; np++) {  // two n8 tiles per ldsm4
                uint32_t r0, r1, r2, r3;
                if (!BNN) {
                    int row = wn * WNT + np * 16 + (lane & 7) + ((lane >> 4) & 1) * 8;
                    int col = kk * 16 + ((lane >> 3) & 1) * 8;
                    ldsm4(r0, r1, r2, r3, s2u(&Bs[row][col]));
                } else {
                    int row = kk * 16 + (lane & 7) + ((lane >> 3) & 1) * 8;
                    int col = wn * WNT + np * 16 + ((lane >> 4) & 1) * 8;
                    ldsm4t(r0, r1, r2, r3, s2u(&Bs[row][col]));
                }
                b[np * 2][0] = r0; b[np * 2][1] = r1;
                b[np * 2 + 1][0] = r2; b[np * 2 + 1][1] = r3;
            }
            #pragma unroll
            for (int mi = 0; mi < MI; mi++)
                #pragma unroll
                for (int ni = 0; ni < NI; ni++)
                    mma16816(c[mi][ni], a[mi], b[ni]);
        }
        __syncthreads();
    }

    // Epilogue
    float* Cf = (float*)Cout + (size_t)blockIdx.z * cZ;
    __nv_bfloat16* Cb = (__nv_bfloat16*)Cout + (size_t)blockIdx.z * cZ;
    #pragma unroll
    for (int mi = 0; mi < MI; mi++) {
        int rbase = i0 + wm * WMT + mi * 16 + (lane >> 2);
        #pragma unroll
        for (int ni = 0; ni < NI; ni++) {
            int col = n0 + wn * WNT + ni * 8 + (lane & 3) * 2;
            #pragma unroll
            for (int h = 0; h < 2; h++) {
                int r = rbase + h * 8;
                float v0 = c[mi][ni][h * 2 + 0] * alpha;
                float v1 = c[mi][ni][h * 2 + 1] * alpha;
                if (EPI >= 1) { v0 += bias[col]; v1 += bias[col + 1]; }
                if (EPI == 2) {
                    v0 = 0.5f * v0 * (1.0f + erff(v0 * 0.70710678118654752f));
                    v1 = 0.5f * v1 * (1.0f + erff(v1 * 0.70710678118654752f));
                }
                if (EPI == 3) {
                    v0 += res[(size_t)r * ldc + col];
                    v1 += res[(size_t)r * ldc + col + 1];
                }
                if (OBF) {
                    __nv_bfloat162 p;
                    p.x = __float2bfloat16(v0); p.y = __float2bfloat16(v1);
                    *(__nv_bfloat162*)&Cb[(size_t)r * ldc + col] = p;
                } else {
                    float2 p; p.x = v0; p.y = v1;
                    *(float2*)&Cf[(size_t)r * ldc + col] = p;
                }
            }
        }
    }
}

// ---------------------------------------------------------------------------
extern "C" void kernel_launch(void* const* d_in, const int* in_sizes, int n_in,
                              void* d_out, int out_size) {
    const float* x      = (const float*)d_in[0];
    const float* ln1_g  = (const float*)d_in[2];
    const float* ln1_b  = (const float*)d_in[3];
    const float* qkv_w  = (const float*)d_in[4];
    const float* qkv_b  = (const float*)d_in[5];
    const float* proj_w = (const float*)d_in[6];
    const float* proj_b = (const float*)d_in[7];
    const float* ln2_g  = (const float*)d_in[8];
    const float* ln2_b  = (const float*)d_in[9];
    const float* fc1_w  = (const float*)d_in[10];
    const float* fc1_b  = (const float*)d_in[11];
    const float* fc2_w  = (const float*)d_in[12];
    const float* fc2_b  = (const float*)d_in[13];
    float* out = (float*)d_out;

    __nv_bfloat16 *p_ln1, *p_qkv, *p_P, *p_O, *p_ln2, *p_hid;
    __nv_bfloat16 *p_wqkv, *p_wproj, *p_wfc1, *p_wfc2;
    float *p_S, *p_x2;
    cudaGetSymbolAddress((void**)&p_ln1,  g_ln1b);
    cudaGetSymbolAddress((void**)&p_qkv,  g_qkvb);
    cudaGetSymbolAddress((void**)&p_S,    g_S);
    cudaGetSymbolAddress((void**)&p_P,    g_Pb);
    cudaGetSymbolAddress((void**)&p_O,    g_Ob);
    cudaGetSymbolAddress((void**)&p_x2,   g_x2);
    cudaGetSymbolAddress((void**)&p_ln2,  g_ln2b);
    cudaGetSymbolAddress((void**)&p_hid,  g_hidb);
    cudaGetSymbolAddress((void**)&p_wqkv, g_wqkv);
    cudaGetSymbolAddress((void**)&p_wproj,g_wproj);
    cudaGetSymbolAddress((void**)&p_wfc1, g_wfc1);
    cudaGetSymbolAddress((void**)&p_wfc2, g_wfc2);

    // Weight conversions (tiny)
    f2bf<<<(3*CD*CD + 255)/256, 256>>>(qkv_w,  p_wqkv,  3*CD*CD);
    f2bf<<<(CD*CD   + 255)/256, 256>>>(proj_w, p_wproj, CD*CD);
    f2bf<<<(HIDD*CD + 255)/256, 256>>>(fc1_w,  p_wfc1,  HIDD*CD);
    f2bf<<<(CD*HIDD + 255)/256, 256>>>(fc2_w,  p_wfc2,  CD*HIDD);

    // 1. LN1 -> bf16
    ln_kernel<<<LT / 8, 256>>>(x, ln1_g, ln1_b, p_ln1);

    // 2. QKV: [110592,96] @ [96,288]^T + bias -> bf16 [N, B_, 3C] flat
    mma_gemm<128, 96, false, 1, true><<<dim3(3, LT / 128, 1), 256>>>(
        p_ln1, CD, 0, p_wqkv, CD, 0, qkv_b, nullptr, p_qkv, 3 * CD, 0, CD, 1.0f);

    // 3. Logits: S[h] = scale * Q[h] @ K[h]^T   (Q at +h*1536, K at +4608+h*1536)
    mma_gemm<128, 128, false, 0, false><<<dim3(NS / 128, NS / 128, NHD), 256>>>(
        p_qkv, 3 * CD * 48, DA, p_qkv + 3 * DA, 3 * CD * 48, DA,
        nullptr, nullptr, p_S, NS, (long)NS * NS, DA, QK_SCALE);

    // 4. Softmax fp32 -> bf16 probs
    softmax_kernel<<<NHD * NS, 256>>>(p_S, p_P);

    // 5. O[h] = P[h] @ V[h]   (V at +9216+h*1536), out bf16 flat [110592,96]
    mma_gemm<128, 128, true, 0, true><<<dim3(DA / 128, NS / 128, NHD), 256>>>(
        p_P, NS, (long)NS * NS, p_qkv + 6 * DA, 3 * CD * 48, DA,
        nullptr, nullptr, p_O, NHD * DA, DA, NS, 1.0f);

    // 6. proj + bias + residual(x) -> fp32 g_x2
    mma_gemm<128, 96, false, 3, false><<<dim3(1, LT / 128, 1), 256>>>(
        p_O, CD, 0, p_wproj, CD, 0, proj_b, x, p_x2, CD, 0, CD, 1.0f);

    // 7. LN2 -> bf16
    ln_kernel<<<LT / 8, 256>>>(p_x2, ln2_g, ln2_b, p_ln2);

    // 8. fc1 + bias + exact GELU -> bf16 hid
    mma_gemm<128, 96, false, 2, true><<<dim3(HIDD / 96, LT / 128, 1), 256>>>(
        p_ln2, CD, 0, p_wfc1, CD, 0, fc1_b, nullptr, p_hid, HIDD, 0, CD, 1.0f);

    // 9. fc2 + bias + residual(g_x2) -> fp32 out
    mma_gemm<128, 96, false, 3, false><<<dim3(1, LT / 128, 1), 256>>>(
        p_hid, HIDD, 0, p_wfc2, HIDD, 0, fc2_b, p_x2, out, CD, 0, HIDD, 1.0f);
}

// round 4
// speedup vs baseline: 6.1968x; 1.2429x over previous
#include <cuda_runtime.h>
#include <cuda_bf16.h>
#include <math.h>
#include <stdint.h>

// Problem constants
#define LT   110592
#define CD   96
#define NS   2304
#define DA   1536
#define NHD  3
#define HIDD 384
#define QK_SCALE 0.17677669529663687f

// Scratch (device globals; alloc APIs banned)
__device__ __nv_bfloat16 g_ln1b[(size_t)LT * CD];
__device__ __nv_bfloat16 g_qkvb[(size_t)LT * 3 * CD];
__device__ float         g_S   [(size_t)NHD * NS * NS];
__device__ __nv_bfloat16 g_Pb  [(size_t)NHD * NS * NS];
__device__ __nv_bfloat16 g_Ob  [(size_t)NS * NHD * DA];
__device__ float         g_x2  [(size_t)LT * CD];
__device__ __nv_bfloat16 g_ln2b[(size_t)LT * CD];
__device__ __nv_bfloat16 g_hidb[(size_t)LT * HIDD];
__device__ __nv_bfloat16 g_wqkv[3 * CD * CD];
__device__ __nv_bfloat16 g_wproj[CD * CD];
__device__ __nv_bfloat16 g_wfc1[HIDD * CD];
__device__ __nv_bfloat16 g_wfc2[CD * HIDD];

// ---------------------------------------------------------------------------
__device__ __forceinline__ uint32_t s2u(const void* p) {
    return (uint32_t)__cvta_generic_to_shared(p);
}
__device__ __forceinline__ void ldsm4(uint32_t& r0, uint32_t& r1, uint32_t& r2, uint32_t& r3, uint32_t a) {
    asm volatile("ldmatrix.sync.aligned.m8n8.x4.shared.b16 {%0,%1,%2,%3}, [%4];\n"
                 : "=r"(r0), "=r"(r1), "=r"(r2), "=r"(r3) : "r"(a));
}
__device__ __forceinline__ void ldsm4t(uint32_t& r0, uint32_t& r1, uint32_t& r2, uint32_t& r3, uint32_t a) {
    asm volatile("ldmatrix.sync.aligned.m8n8.x4.trans.shared.b16 {%0,%1,%2,%3}, [%4];\n"
                 : "=r"(r0), "=r"(r1), "=r"(r2), "=r"(r3) : "r"(a));
}
__device__ __forceinline__ void mma16816(float* c, const uint32_t* a, const uint32_t* b) {
    asm volatile("mma.sync.aligned.m16n8k16.row.col.f32.bf16.bf16.f32 "
                 "{%0,%1,%2,%3}, {%4,%5,%6,%7}, {%8,%9}, {%0,%1,%2,%3};\n"
                 : "+f"(c[0]), "+f"(c[1]), "+f"(c[2]), "+f"(c[3])
                 : "r"(a[0]), "r"(a[1]), "r"(a[2]), "r"(a[3]), "r"(b[0]), "r"(b[1]));
}
__device__ __forceinline__ void cpa16(uint32_t dst, const void* src) {
    asm volatile("cp.async.cg.shared.global [%0], [%1], 16;\n" :: "r"(dst), "l"(src));
}
__device__ __forceinline__ void cpa_commit() {
    asm volatile("cp.async.commit_group;\n" ::: "memory");
}
__device__ __forceinline__ void cpa_wait1() {
    asm volatile("cp.async.wait_group 1;\n" ::: "memory");
}

// ---------------------------------------------------------------------------
// LayerNorm: one warp per row of 96, bf16 out
// ---------------------------------------------------------------------------
__global__ void ln_kernel(const float* __restrict__ x, const float* __restrict__ g,
                          const float* __restrict__ b, __nv_bfloat16* __restrict__ out) {
    int wid  = (blockIdx.x * blockDim.x + threadIdx.x) >> 5;
    int lane = threadIdx.x & 31;
    if (wid >= LT) return;
    const float* row = x + (size_t)wid * CD;
    float v0 = row[lane], v1 = row[lane + 32], v2 = row[lane + 64];
    float s = v0 + v1 + v2;
    #pragma unroll
    for (int o = 16; o > 0; o >>= 1) s += __shfl_xor_sync(0xffffffffu, s, o);
    float mean = s * (1.0f / 96.0f);
    float d0 = v0 - mean, d1 = v1 - mean, d2 = v2 - mean;
    float vs = d0 * d0 + d1 * d1 + d2 * d2;
    #pragma unroll
    for (int o = 16; o > 0; o >>= 1) vs += __shfl_xor_sync(0xffffffffu, vs, o);
    float rstd = rsqrtf(vs * (1.0f / 96.0f) + 1e-5f);
    __nv_bfloat16* orow = out + (size_t)wid * CD;
    orow[lane]      = __float2bfloat16(d0 * rstd * g[lane]      + b[lane]);
    orow[lane + 32] = __float2bfloat16(d1 * rstd * g[lane + 32] + b[lane + 32]);
    orow[lane + 64] = __float2bfloat16(d2 * rstd * g[lane + 64] + b[lane + 64]);
}

__global__ void f2bf(const float* __restrict__ s, __nv_bfloat16* __restrict__ d, int n) {
    int i = blockIdx.x * blockDim.x + threadIdx.x;
    if (i < n) d[i] = __float2bfloat16(s[i]);
}

// ---------------------------------------------------------------------------
// Row softmax over 2304 cols (fp32 in, bf16 out)
// ---------------------------------------------------------------------------
__global__ void softmax_kernel(const float* __restrict__ S, __nv_bfloat16* __restrict__ P) {
    const int row = blockIdx.x;
    const float* p = S + (size_t)row * NS;
    __nv_bfloat16* q = P + (size_t)row * NS;
    const int tid = threadIdx.x;
    __shared__ float sm[8], ss[8];

    float v[9];
    float mx = -3.4e38f;
    #pragma unroll
    for (int i = 0; i < 9; i++) { v[i] = p[tid + 256 * i]; mx = fmaxf(mx, v[i]); }
    #pragma unroll
    for (int o = 16; o > 0; o >>= 1) mx = fmaxf(mx, __shfl_xor_sync(0xffffffffu, mx, o));
    if ((tid & 31) == 0) sm[tid >> 5] = mx;
    __syncthreads();
    mx = sm[0];
    #pragma unroll
    for (int i = 1; i < 8; i++) mx = fmaxf(mx, sm[i]);

    float sum = 0.0f;
    #pragma unroll
    for (int i = 0; i < 9; i++) { v[i] = __expf(v[i] - mx); sum += v[i]; }
    #pragma unroll
    for (int o = 16; o > 0; o >>= 1) sum += __shfl_xor_sync(0xffffffffu, sum, o);
    if ((tid & 31) == 0) ss[tid >> 5] = sum;
    __syncthreads();
    sum = 0.0f;
    #pragma unroll
    for (int i = 0; i < 8; i++) sum += ss[i];
    float inv = 1.0f / sum;
    #pragma unroll
    for (int i = 0; i < 9; i++) q[tid + 256 * i] = __float2bfloat16(v[i] * inv);
}

// ---------------------------------------------------------------------------
// bf16 warp-MMA GEMM with 3-stage cp.async pipeline.
//   C = alpha * A @ op(B) (+ epilogue)
//   BNN=false: B [N,K] (NT) ; BNN=true: B [K,N] (NN)
// EPI: 0 none, 1 +bias, 2 +bias+gelu, 3 +bias+residual ; OBF: bf16 vs fp32 out
// ---------------------------------------------------------------------------
template<int BM, int BN, bool BNN, int EPI, bool OBF>
__global__ void __launch_bounds__(256) mma_gemm(
    const __nv_bfloat16* __restrict__ A, int lda, long aZ,
    const __nv_bfloat16* __restrict__ B, int ldb, long bZ,
    const float* __restrict__ bias, const float* __restrict__ res,
    void* __restrict__ Cout, int ldc, long cZ, int K, float alpha)
{
    constexpr int BK = 32, SA = BK + 8;
    constexpr int WM = 4, WN = 2;
    constexpr int WMT = BM / WM;         // 32
    constexpr int WNT = BN / WN;         // 64 / 48
    constexpr int MI = WMT / 16;         // 2
    constexpr int NI = WNT / 8;          // 8 / 6
    constexpr int THREADS = 256;
    constexpr int BSR = BNN ? BK : BN;
    constexpr int BSC = BNN ? BN + 8 : SA;
    constexpr int STAGE = BM * SA + BSR * BSC;   // elements per stage

    extern __shared__ __nv_bfloat16 smp[];

    const int tid  = threadIdx.x;
    const int wid  = tid >> 5;
    const int lane = tid & 31;
    const int wm = wid / WN, wn = wid % WN;
    const int i0 = blockIdx.y * BM;
    const int n0 = blockIdx.x * BN;
    A += (size_t)blockIdx.z * aZ + (size_t)i0 * lda;
    if (!BNN) B += (size_t)blockIdx.z * bZ + (size_t)n0 * ldb;
    else      B += (size_t)blockIdx.z * bZ + n0;

    float c[MI][NI][4];
    #pragma unroll
    for (int mi = 0; mi < MI; mi++)
        #pragma unroll
        for (int ni = 0; ni < NI; ni++)
            #pragma unroll
            for (int e = 0; e < 4; e++) c[mi][ni][e] = 0.0f;

    const int nKT = K / BK;

    auto load_stage = [&](int kt, int st) {
        __nv_bfloat16* As = smp + st * STAGE;
        __nv_bfloat16* Bs = As + BM * SA;
        const __nv_bfloat16* Ag = A + kt * BK;
        for (int e = tid; e < BM * 4; e += THREADS) {
            int m = e >> 2, kv = e & 3;
            cpa16(s2u(As + m * SA + kv * 8), Ag + (size_t)m * lda + kv * 8);
        }
        if (!BNN) {
            const __nv_bfloat16* Bg = B + kt * BK;
            for (int e = tid; e < BN * 4; e += THREADS) {
                int n = e >> 2, kv = e & 3;
                cpa16(s2u(Bs + n * SA + kv * 8), Bg + (size_t)n * ldb + kv * 8);
            }
        } else {
            const __nv_bfloat16* Bg = B + (size_t)kt * BK * ldb;
            for (int e = tid; e < BK * (BN / 8); e += THREADS) {
                int k = e / (BN / 8), nv = e % (BN / 8);
                cpa16(s2u(Bs + k * (BN + 8) + nv * 8), Bg + (size_t)k * ldb + nv * 8);
            }
        }
    };

    // prologue: stages 0 and 1 in flight
    load_stage(0, 0); cpa_commit();
    load_stage(1, 1); cpa_commit();

    for (int kt = 0; kt < nKT; kt++) {
        cpa_wait1();          // stage kt complete (<=1 younger group pending)
        __syncthreads();

        const int st = kt % 3;
        __nv_bfloat16* As = smp + st * STAGE;
        __nv_bfloat16* Bs = As + BM * SA;

        #pragma unroll
        for (int kk = 0; kk < 2; kk++) {
            uint32_t a[MI][4];
            #pragma unroll
            for (int mi = 0; mi < MI; mi++) {
                int m  = wm * WMT + mi * 16 + (lane & 15);
                int kc = kk * 16 + (lane >> 4) * 8;
                ldsm4(a[mi][0], a[mi][1], a[mi][2], a[mi][3], s2u(As + m * SA + kc));
            }
            uint32_t b[NI][2];
            #pragma unroll
            for (int np = 0; np < NI / 2; np++) {
                uint32_t r0, r1, r2, r3;
                if (!BNN) {
                    int row = wn * WNT + np * 16 + (lane & 7) + ((lane >> 4) & 1) * 8;
                    int col = kk * 16 + ((lane >> 3) & 1) * 8;
                    ldsm4(r0, r1, r2, r3, s2u(Bs + row * SA + col));
                } else {
                    int row = kk * 16 + (lane & 7) + ((lane >> 3) & 1) * 8;
                    int col = wn * WNT + np * 16 + ((lane >> 4) & 1) * 8;
                    ldsm4t(r0, r1, r2, r3, s2u(Bs + row * (BN + 8) + col));
                }
                b[np * 2][0] = r0; b[np * 2][1] = r1;
                b[np * 2 + 1][0] = r2; b[np * 2 + 1][1] = r3;
            }
            #pragma unroll
            for (int mi = 0; mi < MI; mi++)
                #pragma unroll
                for (int ni = 0; ni < NI; ni++)
                    mma16816(c[mi][ni], a[mi], b[ni]);
        }

        // prefetch stage kt+2 (safe: laggard warps read stage kt%3 only)
        if (kt + 2 < nKT) load_stage(kt + 2, (kt + 2) % 3);
        cpa_commit();        // always commit (possibly empty group) to keep count
    }

    // Epilogue
    float* Cf = (float*)Cout + (size_t)blockIdx.z * cZ;
    __nv_bfloat16* Cb = (__nv_bfloat16*)Cout + (size_t)blockIdx.z * cZ;
    #pragma unroll
    for (int mi = 0; mi < MI; mi++) {
        int rbase = i0 + wm * WMT + mi * 16 + (lane >> 2);
        #pragma unroll
        for (int ni = 0; ni < NI; ni++) {
            int col = n0 + wn * WNT + ni * 8 + (lane & 3) * 2;
            #pragma unroll
            for (int hh = 0; hh < 2; hh++) {
                int r = rbase + hh * 8;
                float v0 = c[mi][ni][hh * 2 + 0] * alpha;
                float v1 = c[mi][ni][hh * 2 + 1] * alpha;
                if (EPI >= 1) { v0 += bias[col]; v1 += bias[col + 1]; }
                if (EPI == 2) {
                    v0 = 0.5f * v0 * (1.0f + erff(v0 * 0.70710678118654752f));
                    v1 = 0.5f * v1 * (1.0f + erff(v1 * 0.70710678118654752f));
                }
                if (EPI == 3) {
                    v0 += res[(size_t)r * ldc + col];
                    v1 += res[(size_t)r * ldc + col + 1];
                }
                if (OBF) {
                    __nv_bfloat162 p;
                    p.x = __float2bfloat16(v0); p.y = __float2bfloat16(v1);
                    *(__nv_bfloat162*)&Cb[(size_t)r * ldc + col] = p;
                } else {
                    float2 p; p.x = v0; p.y = v1;
                    *(float2*)&Cf[(size_t)r * ldc + col] = p;
                }
            }
        }
    }
}

// ---------------------------------------------------------------------------
extern "C" void kernel_launch(void* const* d_in, const int* in_sizes, int n_in,
                              void* d_out, int out_size) {
    const float* x      = (const float*)d_in[0];
    const float* ln1_g  = (const float*)d_in[2];
    const float* ln1_b  = (const float*)d_in[3];
    const float* qkv_w  = (const float*)d_in[4];
    const float* qkv_b  = (const float*)d_in[5];
    const float* proj_w = (const float*)d_in[6];
    const float* proj_b = (const float*)d_in[7];
    const float* ln2_g  = (const float*)d_in[8];
    const float* ln2_b  = (const float*)d_in[9];
    const float* fc1_w  = (const float*)d_in[10];
    const float* fc1_b  = (const float*)d_in[11];
    const float* fc2_w  = (const float*)d_in[12];
    const float* fc2_b  = (const float*)d_in[13];
    float* out = (float*)d_out;

    __nv_bfloat16 *p_ln1, *p_qkv, *p_P, *p_O, *p_ln2, *p_hid;
    __nv_bfloat16 *p_wqkv, *p_wproj, *p_wfc1, *p_wfc2;
    float *p_S, *p_x2;
    cudaGetSymbolAddress((void**)&p_ln1,  g_ln1b);
    cudaGetSymbolAddress((void**)&p_qkv,  g_qkvb);
    cudaGetSymbolAddress((void**)&p_S,    g_S);
    cudaGetSymbolAddress((void**)&p_P,    g_Pb);
    cudaGetSymbolAddress((void**)&p_O,    g_Ob);
    cudaGetSymbolAddress((void**)&p_x2,   g_x2);
    cudaGetSymbolAddress((void**)&p_ln2,  g_ln2b);
    cudaGetSymbolAddress((void**)&p_hid,  g_hidb);
    cudaGetSymbolAddress((void**)&p_wqkv, g_wqkv);
    cudaGetSymbolAddress((void**)&p_wproj,g_wproj);
    cudaGetSymbolAddress((void**)&p_wfc1, g_wfc1);
    cudaGetSymbolAddress((void**)&p_wfc2, g_wfc2);

    // dynamic SMEM sizes (bytes): 3 stages x (A + B) bf16
    const int SM_NT128 = 3 * (128 * 40 + 128 * 40) * 2;  // 61440
    const int SM_NT96  = 3 * (128 * 40 + 96 * 40) * 2;   // 53760
    const int SM_NN128 = 3 * (128 * 40 + 32 * 136) * 2;  // 56832
    cudaFuncSetAttribute(mma_gemm<128, 96, false, 1, true>,
                         cudaFuncAttributeMaxDynamicSharedMemorySize, SM_NT96);
    cudaFuncSetAttribute(mma_gemm<128, 128, false, 0, false>,
                         cudaFuncAttributeMaxDynamicSharedMemorySize, SM_NT128);
    cudaFuncSetAttribute(mma_gemm<128, 128, true, 0, true>,
                         cudaFuncAttributeMaxDynamicSharedMemorySize, SM_NN128);
    cudaFuncSetAttribute(mma_gemm<128, 96, false, 3, false>,
                         cudaFuncAttributeMaxDynamicSharedMemorySize, SM_NT96);
    cudaFuncSetAttribute(mma_gemm<128, 96, false, 2, true>,
                         cudaFuncAttributeMaxDynamicSharedMemorySize, SM_NT96);

    // weights -> bf16
    f2bf<<<(3*CD*CD + 255)/256, 256>>>(qkv_w,  p_wqkv,  3*CD*CD);
    f2bf<<<(CD*CD   + 255)/256, 256>>>(proj_w, p_wproj, CD*CD);
    f2bf<<<(HIDD*CD + 255)/256, 256>>>(fc1_w,  p_wfc1,  HIDD*CD);
    f2bf<<<(CD*HIDD + 255)/256, 256>>>(fc2_w,  p_wfc2,  CD*HIDD);

    // 1. LN1 -> bf16
    ln_kernel<<<LT / 8, 256>>>(x, ln1_g, ln1_b, p_ln1);

    // 2. QKV: [110592,96]@[96,288]^T + bias -> bf16 [N, B_, 3C] flat
    mma_gemm<128, 96, false, 1, true><<<dim3(3, LT / 128, 1), 256, SM_NT96>>>(
        p_ln1, CD, 0, p_wqkv, CD, 0, qkv_b, nullptr, p_qkv, 3 * CD, 0, CD, 1.0f);

    // 3. Logits: S[h] = scale * Q[h] @ K[h]^T
    mma_gemm<128, 128, false, 0, false><<<dim3(NS / 128, NS / 128, NHD), 256, SM_NT128>>>(
        p_qkv, 3 * CD * 48, DA, p_qkv + 3 * DA, 3 * CD * 48, DA,
        nullptr, nullptr, p_S, NS, (long)NS * NS, DA, QK_SCALE);

    // 4. Softmax fp32 -> bf16 probs
    softmax_kernel<<<NHD * NS, 256>>>(p_S, p_P);

    // 5. O[h] = P[h] @ V[h] (NN)
    mma_gemm<128, 128, true, 0, true><<<dim3(DA / 128, NS / 128, NHD), 256, SM_NN128>>>(
        p_P, NS, (long)NS * NS, p_qkv + 6 * DA, 3 * CD * 48, DA,
        nullptr, nullptr, p_O, NHD * DA, DA, NS, 1.0f);

    // 6. proj + bias + residual(x) -> fp32 g_x2
    mma_gemm<128, 96, false, 3, false><<<dim3(1, LT / 128, 1), 256, SM_NT96>>>(
        p_O, CD, 0, p_wproj, CD, 0, proj_b, x, p_x2, CD, 0, CD, 1.0f);

    // 7. LN2 -> bf16
    ln_kernel<<<LT / 8, 256>>>(p_x2, ln2_g, ln2_b, p_ln2);

    // 8. fc1 + bias + GELU -> bf16 hid
    mma_gemm<128, 96, false, 2, true><<<dim3(HIDD / 96, LT / 128, 1), 256, SM_NT96>>>(
        p_ln2, CD, 0, p_wfc1, CD, 0, fc1_b, nullptr, p_hid, HIDD, 0, CD, 1.0f);

    // 9. fc2 + bias + residual(g_x2) -> fp32 out
    mma_gemm<128, 96, false, 3, false><<<dim3(1, LT / 128, 1), 256, SM_NT96>>>(
        p_hid, HIDD, 0, p_wfc2, HIDD, 0, fc2_b, p_x2, out, CD, 0, HIDD, 1.0f);
}

// round 5
// speedup vs baseline: 6.3515x; 1.0250x over previous
#include <cuda_runtime.h>
#include <cuda_bf16.h>
#include <math.h>
#include <stdint.h>

// Problem constants
#define LT   110592
#define CD   96
#define NS   2304
#define DA   1536
#define NHD  3
#define HIDD 384
#define QK_SCALE 0.17677669529663687f

// Scratch (device globals; alloc APIs banned)
__device__ __nv_bfloat16 g_ln1b[(size_t)LT * CD];
__device__ __nv_bfloat16 g_qkvb[(size_t)LT * 3 * CD];
__device__ float         g_S   [(size_t)NHD * NS * NS];
__device__ __nv_bfloat16 g_Pb  [(size_t)NHD * NS * NS];
__device__ __nv_bfloat16 g_Ob  [(size_t)NS * NHD * DA];
__device__ float         g_x2  [(size_t)LT * CD];
__device__ __nv_bfloat16 g_ln2b[(size_t)LT * CD];
__device__ __nv_bfloat16 g_hidb[(size_t)LT * HIDD];
__device__ __nv_bfloat16 g_wall[110592];   // all 4 weight mats bf16, packed

// packed weight offsets
#define W_QKV  0
#define W_PROJ (3 * CD * CD)                    // 27648
#define W_FC1  (W_PROJ + CD * CD)               // 36864
#define W_FC2  (W_FC1 + HIDD * CD)              // 73728
#define W_TOT  (W_FC2 + CD * HIDD)              // 110592

// ---------------------------------------------------------------------------
__device__ __forceinline__ uint32_t s2u(const void* p) {
    return (uint32_t)__cvta_generic_to_shared(p);
}
__device__ __forceinline__ void ldsm4(uint32_t& r0, uint32_t& r1, uint32_t& r2, uint32_t& r3, uint32_t a) {
    asm volatile("ldmatrix.sync.aligned.m8n8.x4.shared.b16 {%0,%1,%2,%3}, [%4];\n"
                 : "=r"(r0), "=r"(r1), "=r"(r2), "=r"(r3) : "r"(a));
}
__device__ __forceinline__ void ldsm4t(uint32_t& r0, uint32_t& r1, uint32_t& r2, uint32_t& r3, uint32_t a) {
    asm volatile("ldmatrix.sync.aligned.m8n8.x4.trans.shared.b16 {%0,%1,%2,%3}, [%4];\n"
                 : "=r"(r0), "=r"(r1), "=r"(r2), "=r"(r3) : "r"(a));
}
__device__ __forceinline__ void mma16816(float* c, const uint32_t* a, const uint32_t* b) {
    asm volatile("mma.sync.aligned.m16n8k16.row.col.f32.bf16.bf16.f32 "
                 "{%0,%1,%2,%3}, {%4,%5,%6,%7}, {%8,%9}, {%0,%1,%2,%3};\n"
                 : "+f"(c[0]), "+f"(c[1]), "+f"(c[2]), "+f"(c[3])
                 : "r"(a[0]), "r"(a[1]), "r"(a[2]), "r"(a[3]), "r"(b[0]), "r"(b[1]));
}
__device__ __forceinline__ void cpa16(uint32_t dst, const void* src) {
    asm volatile("cp.async.cg.shared.global [%0], [%1], 16;\n" :: "r"(dst), "l"(src));
}
__device__ __forceinline__ void cpa_commit() {
    asm volatile("cp.async.commit_group;\n" ::: "memory");
}
__device__ __forceinline__ void cpa_wait2() {
    asm volatile("cp.async.wait_group 2;\n" ::: "memory");
}

// ---------------------------------------------------------------------------
// LayerNorm: one warp per row of 96, bf16 out
// ---------------------------------------------------------------------------
__global__ void ln_kernel(const float* __restrict__ x, const float* __restrict__ g,
                          const float* __restrict__ b, __nv_bfloat16* __restrict__ out) {
    int wid  = (blockIdx.x * blockDim.x + threadIdx.x) >> 5;
    int lane = threadIdx.x & 31;
    if (wid >= LT) return;
    const float* row = x + (size_t)wid * CD;
    float v0 = row[lane], v1 = row[lane + 32], v2 = row[lane + 64];
    float s = v0 + v1 + v2;
    #pragma unroll
    for (int o = 16; o > 0; o >>= 1) s += __shfl_xor_sync(0xffffffffu, s, o);
    float mean = s * (1.0f / 96.0f);
    float d0 = v0 - mean, d1 = v1 - mean, d2 = v2 - mean;
    float vs = d0 * d0 + d1 * d1 + d2 * d2;
    #pragma unroll
    for (int o = 16; o > 0; o >>= 1) vs += __shfl_xor_sync(0xffffffffu, vs, o);
    float rstd = rsqrtf(vs * (1.0f / 96.0f) + 1e-5f);
    __nv_bfloat16* orow = out + (size_t)wid * CD;
    orow[lane]      = __float2bfloat16(d0 * rstd * g[lane]      + b[lane]);
    orow[lane + 32] = __float2bfloat16(d1 * rstd * g[lane + 32] + b[lane + 32]);
    orow[lane + 64] = __float2bfloat16(d2 * rstd * g[lane + 64] + b[lane + 64]);
}

// single fused weight conversion: 4 segments packed into g_wall
__global__ void f2bf_all(const float* __restrict__ qkv, const float* __restrict__ proj,
                         const float* __restrict__ fc1, const float* __restrict__ fc2,
                         __nv_bfloat16* __restrict__ d) {
    int i = blockIdx.x * blockDim.x + threadIdx.x;
    if (i >= W_TOT) return;
    float v;
    if      (i < W_PROJ) v = qkv[i];
    else if (i < W_FC1)  v = proj[i - W_PROJ];
    else if (i < W_FC2)  v = fc1[i - W_FC1];
    else                 v = fc2[i - W_FC2];
    d[i] = __float2bfloat16(v);
}

// ---------------------------------------------------------------------------
// Row softmax over 2304 cols (fp32 in, bf16 out)
// ---------------------------------------------------------------------------
__global__ void softmax_kernel(const float* __restrict__ S, __nv_bfloat16* __restrict__ P) {
    const int row = blockIdx.x;
    const float* p = S + (size_t)row * NS;
    __nv_bfloat16* q = P + (size_t)row * NS;
    const int tid = threadIdx.x;
    __shared__ float sm[8], ss[8];

    float v[9];
    float mx = -3.4e38f;
    #pragma unroll
    for (int i = 0; i < 9; i++) { v[i] = p[tid + 256 * i]; mx = fmaxf(mx, v[i]); }
    #pragma unroll
    for (int o = 16; o > 0; o >>= 1) mx = fmaxf(mx, __shfl_xor_sync(0xffffffffu, mx, o));
    if ((tid & 31) == 0) sm[tid >> 5] = mx;
    __syncthreads();
    mx = sm[0];
    #pragma unroll
    for (int i = 1; i < 8; i++) mx = fmaxf(mx, sm[i]);

    float sum = 0.0f;
    #pragma unroll
    for (int i = 0; i < 9; i++) { v[i] = __expf(v[i] - mx); sum += v[i]; }
    #pragma unroll
    for (int o = 16; o > 0; o >>= 1) sum += __shfl_xor_sync(0xffffffffu, sum, o);
    if ((tid & 31) == 0) ss[tid >> 5] = sum;
    __syncthreads();
    sum = 0.0f;
    #pragma unroll
    for (int i = 0; i < 8; i++) sum += ss[i];
    float inv = 1.0f / sum;
    #pragma unroll
    for (int i = 0; i < 9; i++) q[tid + 256 * i] = __float2bfloat16(v[i] * inv);
}

// ---------------------------------------------------------------------------
// bf16 warp-MMA GEMM, 4-stage cp.async pipeline, 2 CTAs/SM.
//   C = alpha * A @ op(B) (+ epilogue)
//   BNN=false: B [N,K] (NT) ; BNN=true: B [K,N] (NN)
// EPI: 0 none, 1 +bias, 2 +bias+gelu, 3 +bias+residual ; OBF: bf16 vs fp32 out
// ---------------------------------------------------------------------------
template<int BM, int BN, bool BNN, int EPI, bool OBF>
__global__ void __launch_bounds__(256, 2) mma_gemm(
    const __nv_bfloat16* __restrict__ A, int lda, long aZ,
    const __nv_bfloat16* __restrict__ B, int ldb, long bZ,
    const float* __restrict__ bias, const float* __restrict__ res,
    void* __restrict__ Cout, int ldc, long cZ, int K, float alpha)
{
    constexpr int BK = 32, SA = BK + 8;
    constexpr int WM = 4, WN = 2;
    constexpr int WMT = BM / WM;         // 32
    constexpr int WNT = BN / WN;         // 64 / 48
    constexpr int MI = WMT / 16;         // 2
    constexpr int NI = WNT / 8;          // 8 / 6
    constexpr int THREADS = 256;
    constexpr int BSR = BNN ? BK : BN;
    constexpr int BSC = BNN ? BN + 8 : SA;
    constexpr int STAGE = BM * SA + BSR * BSC;   // elements per stage
    constexpr int NSTG = 4;

    extern __shared__ __nv_bfloat16 smp[];

    const int tid  = threadIdx.x;
    const int wid  = tid >> 5;
    const int lane = tid & 31;
    const int wm = wid / WN, wn = wid % WN;
    const int i0 = blockIdx.y * BM;
    const int n0 = blockIdx.x * BN;
    A += (size_t)blockIdx.z * aZ + (size_t)i0 * lda;
    if (!BNN) B += (size_t)blockIdx.z * bZ + (size_t)n0 * ldb;
    else      B += (size_t)blockIdx.z * bZ + n0;

    float c[MI][NI][4];
    #pragma unroll
    for (int mi = 0; mi < MI; mi++)
        #pragma unroll
        for (int ni = 0; ni < NI; ni++)
            #pragma unroll
            for (int e = 0; e < 4; e++) c[mi][ni][e] = 0.0f;

    const int nKT = K / BK;

    auto load_stage = [&](int kt, int st) {
        __nv_bfloat16* As = smp + st * STAGE;
        __nv_bfloat16* Bs = As + BM * SA;
        const __nv_bfloat16* Ag = A + kt * BK;
        for (int e = tid; e < BM * 4; e += THREADS) {
            int m = e >> 2, kv = e & 3;
            cpa16(s2u(As + m * SA + kv * 8), Ag + (size_t)m * lda + kv * 8);
        }
        if (!BNN) {
            const __nv_bfloat16* Bg = B + kt * BK;
            for (int e = tid; e < BN * 4; e += THREADS) {
                int n = e >> 2, kv = e & 3;
                cpa16(s2u(Bs + n * SA + kv * 8), Bg + (size_t)n * ldb + kv * 8);
            }
        } else {
            const __nv_bfloat16* Bg = B + (size_t)kt * BK * ldb;
            for (int e = tid; e < BK * (BN / 8); e += THREADS) {
                int k = e / (BN / 8), nv = e % (BN / 8);
                cpa16(s2u(Bs + k * (BN + 8) + nv * 8), Bg + (size_t)k * ldb + nv * 8);
            }
        }
    };

    // prologue: 3 stages in flight
    load_stage(0, 0); cpa_commit();
    if (nKT > 1) load_stage(1, 1);
    cpa_commit();
    if (nKT > 2) load_stage(2, 2);
    cpa_commit();

    for (int kt = 0; kt < nKT; kt++) {
        cpa_wait2();          // stage kt complete (<=2 younger groups pending)
        __syncthreads();

        // prefetch stage kt+3 FIRST (gets loads into the memory system early)
        if (kt + 3 < nKT) load_stage(kt + 3, (kt + 3) % NSTG);
        cpa_commit();         // always commit to keep group accounting

        const int st = kt % NSTG;
        __nv_bfloat16* As = smp + st * STAGE;
        __nv_bfloat16* Bs = As + BM * SA;

        #pragma unroll
        for (int kk = 0; kk < 2; kk++) {
            uint32_t a[MI][4];
            #pragma unroll
            for (int mi = 0; mi < MI; mi++) {
                int m  = wm * WMT + mi * 16 + (lane & 15);
                int kc = kk * 16 + (lane >> 4) * 8;
                ldsm4(a[mi][0], a[mi][1], a[mi][2], a[mi][3], s2u(As + m * SA + kc));
            }
            uint32_t b[NI][2];
            #pragma unroll
            for (int np = 0; np < NI / 2; np++) {
                uint32_t r0, r1, r2, r3;
                if (!BNN) {
                    int row = wn * WNT + np * 16 + (lane & 7) + ((lane >> 4) & 1) * 8;
                    int col = kk * 16 + ((lane >> 3) & 1) * 8;
                    ldsm4(r0, r1, r2, r3, s2u(Bs + row * SA + col));
                } else {
                    int row = kk * 16 + (lane & 7) + ((lane >> 3) & 1) * 8;
                    int col = wn * WNT + np * 16 + ((lane >> 4) & 1) * 8;
                    ldsm4t(r0, r1, r2, r3, s2u(Bs + row * (BN + 8) + col));
                }
                b[np * 2][0] = r0; b[np * 2][1] = r1;
                b[np * 2 + 1][0] = r2; b[np * 2 + 1][1] = r3;
            }
            #pragma unroll
            for (int mi = 0; mi < MI; mi++)
                #pragma unroll
                for (int ni = 0; ni < NI; ni++)
                    mma16816(c[mi][ni], a[mi], b[ni]);
        }
    }

    // Epilogue
    float* Cf = (float*)Cout + (size_t)blockIdx.z * cZ;
    __nv_bfloat16* Cb = (__nv_bfloat16*)Cout + (size_t)blockIdx.z * cZ;
    #pragma unroll
    for (int mi = 0; mi < MI; mi++) {
        int rbase = i0 + wm * WMT + mi * 16 + (lane >> 2);
        #pragma unroll
        for (int ni = 0; ni < NI; ni++) {
            int col = n0 + wn * WNT + ni * 8 + (lane & 3) * 2;
            #pragma unroll
            for (int hh = 0; hh < 2; hh++) {
                int r = rbase + hh * 8;
                float v0 = c[mi][ni][hh * 2 + 0] * alpha;
                float v1 = c[mi][ni][hh * 2 + 1] * alpha;
                if (EPI >= 1) { v0 += bias[col]; v1 += bias[col + 1]; }
                if (EPI == 2) {
                    v0 = 0.5f * v0 * (1.0f + erff(v0 * 0.70710678118654752f));
                    v1 = 0.5f * v1 * (1.0f + erff(v1 * 0.70710678118654752f));
                }
                if (EPI == 3) {
                    v0 += res[(size_t)r * ldc + col];
                    v1 += res[(size_t)r * ldc + col + 1];
                }
                if (OBF) {
                    __nv_bfloat162 p;
                    p.x = __float2bfloat16(v0); p.y = __float2bfloat16(v1);
                    *(__nv_bfloat162*)&Cb[(size_t)r * ldc + col] = p;
                } else {
                    float2 p; p.x = v0; p.y = v1;
                    *(float2*)&Cf[(size_t)r * ldc + col] = p;
                }
            }
        }
    }
}

// ---------------------------------------------------------------------------
extern "C" void kernel_launch(void* const* d_in, const int* in_sizes, int n_in,
                              void* d_out, int out_size) {
    const float* x      = (const float*)d_in[0];
    const float* ln1_g  = (const float*)d_in[2];
    const float* ln1_b  = (const float*)d_in[3];
    const float* qkv_w  = (const float*)d_in[4];
    const float* qkv_b  = (const float*)d_in[5];
    const float* proj_w = (const float*)d_in[6];
    const float* proj_b = (const float*)d_in[7];
    const float* ln2_g  = (const float*)d_in[8];
    const float* ln2_b  = (const float*)d_in[9];
    const float* fc1_w  = (const float*)d_in[10];
    const float* fc1_b  = (const float*)d_in[11];
    const float* fc2_w  = (const float*)d_in[12];
    const float* fc2_b  = (const float*)d_in[13];
    float* out = (float*)d_out;

    __nv_bfloat16 *p_ln1, *p_qkv, *p_P, *p_O, *p_ln2, *p_hid, *p_w;
    float *p_S, *p_x2;
    cudaGetSymbolAddress((void**)&p_ln1,  g_ln1b);
    cudaGetSymbolAddress((void**)&p_qkv,  g_qkvb);
    cudaGetSymbolAddress((void**)&p_S,    g_S);
    cudaGetSymbolAddress((void**)&p_P,    g_Pb);
    cudaGetSymbolAddress((void**)&p_O,    g_Ob);
    cudaGetSymbolAddress((void**)&p_x2,   g_x2);
    cudaGetSymbolAddress((void**)&p_ln2,  g_ln2b);
    cudaGetSymbolAddress((void**)&p_hid,  g_hidb);
    cudaGetSymbolAddress((void**)&p_w,    g_wall);

    // dynamic SMEM (bytes): 4 stages x (A + B) bf16
    const int SM_NT128 = 4 * (128 * 40 + 128 * 40) * 2;  // 81920
    const int SM_NT96  = 4 * (128 * 40 + 96 * 40) * 2;   // 71680
    const int SM_NN128 = 4 * (128 * 40 + 32 * 136) * 2;  // 75776
    cudaFuncSetAttribute(mma_gemm<128, 96, false, 1, true>,
                         cudaFuncAttributeMaxDynamicSharedMemorySize, SM_NT96);
    cudaFuncSetAttribute(mma_gemm<128, 128, false, 0, false>,
                         cudaFuncAttributeMaxDynamicSharedMemorySize, SM_NT128);
    cudaFuncSetAttribute(mma_gemm<128, 128, true, 0, true>,
                         cudaFuncAttributeMaxDynamicSharedMemorySize, SM_NN128);
    cudaFuncSetAttribute(mma_gemm<128, 96, false, 3, false>,
                         cudaFuncAttributeMaxDynamicSharedMemorySize, SM_NT96);
    cudaFuncSetAttribute(mma_gemm<128, 96, false, 2, true>,
                         cudaFuncAttributeMaxDynamicSharedMemorySize, SM_NT96);

    // weights -> bf16 (one launch)
    f2bf_all<<<(W_TOT + 255)/256, 256>>>(qkv_w, proj_w, fc1_w, fc2_w, p_w);

    // 1. LN1 -> bf16
    ln_kernel<<<LT / 8, 256>>>(x, ln1_g, ln1_b, p_ln1);

    // 2. QKV: [110592,96]@[96,288]^T + bias -> bf16 [N, B_, 3C] flat
    mma_gemm<128, 96, false, 1, true><<<dim3(3, LT / 128, 1), 256, SM_NT96>>>(
        p_ln1, CD, 0, p_w + W_QKV, CD, 0, qkv_b, nullptr, p_qkv, 3 * CD, 0, CD, 1.0f);

    // 3. Logits: S[h] = scale * Q[h] @ K[h]^T
    mma_gemm<128, 128, false, 0, false><<<dim3(NS / 128, NS / 128, NHD), 256, SM_NT128>>>(
        p_qkv, 3 * CD * 48, DA, p_qkv + 3 * DA, 3 * CD * 48, DA,
        nullptr, nullptr, p_S, NS, (long)NS * NS, DA, QK_SCALE);

    // 4. Softmax fp32 -> bf16 probs
    softmax_kernel<<<NHD * NS, 256>>>(p_S, p_P);

    // 5. O[h] = P[h] @ V[h] (NN)
    mma_gemm<128, 128, true, 0, true><<<dim3(DA / 128, NS / 128, NHD), 256, SM_NN128>>>(
        p_P, NS, (long)NS * NS, p_qkv + 6 * DA, 3 * CD * 48, DA,
        nullptr, nullptr, p_O, NHD * DA, DA, NS, 1.0f);

    // 6. proj + bias + residual(x) -> fp32 g_x2
    mma_gemm<128, 96, false, 3, false><<<dim3(1, LT / 128, 1), 256, SM_NT96>>>(
        p_O, CD, 0, p_w + W_PROJ, CD, 0, proj_b, x, p_x2, CD, 0, CD, 1.0f);

    // 7. LN2 -> bf16
    ln_kernel<<<LT / 8, 256>>>(p_x2, ln2_g, ln2_b, p_ln2);

    // 8. fc1 + bias + GELU -> bf16 hid
    mma_gemm<128, 96, false, 2, true><<<dim3(HIDD / 96, LT / 128, 1), 256, SM_NT96>>>(
        p_ln2, CD, 0, p_w + W_FC1, CD, 0, fc1_b, nullptr, p_hid, HIDD, 0, CD, 1.0f);

    // 9. fc2 + bias + residual(g_x2) -> fp32 out
    mma_gemm<128, 96, false, 3, false><<<dim3(1, LT / 128, 1), 256, SM_NT96>>>(
        p_hid, HIDD, 0, p_w + W_FC2, HIDD, 0, fc2_b, p_x2, out, CD, 0, HIDD, 1.0f);
}